// round 16
// baseline (speedup 1.0000x reference)
#include <cuda_runtime.h>
#include <math.h>

// ---------------- problem constants ----------------
// B=16, P=512, S=1024, D=1024, H_FULL=16 (hd=64), H_LIGHT=8 (hd=128)

// ---------------- device scratch ----------------
__device__ float  g_q     [8192u  * 1024u];
__device__ float  g_kv    [16384u * 2048u];
__device__ float  g_qkv   [8192u  * 3072u];
__device__ float2 g_ml    [16u * 16u * 512u];   // cross (m, 1/l) per [b][h][p]
__device__ float  g_ob    [8192u  * 1024u];
__device__ float  g_rw    [8192u  * 1024u];
__device__ float  g_cross [8192u  * 1024u];
__device__ float  g_selfo [8192u  * 1024u];
__device__ float  g_light [8192u  * 1024u];
__device__ float  g_hb    [8192u  * 1024u];

// ---------------- async copy helpers ----------------
__device__ __forceinline__ void cp_async16(void* smem, const void* gmem) {
    unsigned s = (unsigned)__cvta_generic_to_shared(smem);
    asm volatile("cp.async.cg.shared.global [%0], [%1], 16;\n" :: "r"(s), "l"(gmem));
}
__device__ __forceinline__ void cp_commit() { asm volatile("cp.async.commit_group;\n"); }
template<int N> __device__ __forceinline__ void cp_wait() {
    asm volatile("cp.async.wait_group %0;\n" :: "n"(N));
}

__device__ __forceinline__ void mma_tf32(float* d, const float* a, const float* b) {
    const unsigned* A  = reinterpret_cast<const unsigned*>(a);
    const unsigned* Bv = reinterpret_cast<const unsigned*>(b);
    asm volatile(
        "mma.sync.aligned.m16n8k8.row.col.f32.tf32.tf32.f32 "
        "{%0,%1,%2,%3}, {%4,%5,%6,%7}, {%8,%9}, {%0,%1,%2,%3};"
        : "+f"(d[0]), "+f"(d[1]), "+f"(d[2]), "+f"(d[3])
        : "r"(A[0]), "r"(A[1]), "r"(A[2]), "r"(A[3]), "r"(Bv[0]), "r"(Bv[1]));
}

// ---------------- shared GEMM mainloop body (BK=64, warp tile 64x64) ----------------
template<bool GATE, bool GELU>
__device__ __forceinline__ void gemm_body(
    const float* __restrict__ A0, const float* __restrict__ A1,
    const float* __restrict__ A2, int lda,
    const float* __restrict__ B, int ldb,
    float* __restrict__ C, int ldc, int K, const float* __restrict__ bias,
    const float* __restrict__ res, int bm, int bn, float* sm)
{
    constexpr int BM = 128, BN = 256, BK = 64;
    constexpr int ASTR = BK + 4, BSTR = BK + 4;
    constexpr int AEL = BM * ASTR, BEL = BN * BSTR;

    float* As = sm;
    float* Bs = sm + 2 * AEL;

    const int tid = threadIdx.x, warp = tid >> 5, lane = tid & 31;
    const int gid = lane >> 2, tig = lane & 3;
    const int wm = (warp & 1) * 64, wn = (warp >> 1) * 64;

    float acc[4][8][4] = {};

    auto loadA = [&](int buf, int k0) {
        const float* Ab;
        if (GATE) {
            Ab = (k0 < 1024) ? (A0 + k0)
               : (k0 < 2048) ? (A1 + (k0 - 1024))
                             : (A2 + (k0 - 2048));
        } else Ab = A0 + k0;
        #pragma unroll
        for (int i = tid; i < BM * 16; i += 256) {
            int r = i / 16, c = i % 16;
            cp_async16(&As[buf * AEL + r * ASTR + c * 4],
                       Ab + (long long)(bm + r) * lda + c * 4);
        }
    };
    auto loadB = [&](int buf, int k0) {
        #pragma unroll
        for (int i = tid; i < BN * 16; i += 256) {
            int r = i / 16, c = i % 16;
            cp_async16(&Bs[buf * BEL + r * BSTR + c * 4],
                       B + (long long)(bn + r) * ldb + k0 + c * 4);
        }
    };

    const int T = K / BK;
    loadA(0, 0); loadB(0, 0); cp_commit();
    for (int t = 0; t < T; t++) {
        cp_wait<0>();
        __syncthreads();
        if (t + 1 < T) {
            loadA((t + 1) & 1, (t + 1) * BK);
            loadB((t + 1) & 1, (t + 1) * BK);
            cp_commit();
        }
        const float* Ab  = As + (t & 1) * AEL;
        const float* Bb2 = Bs + (t & 1) * BEL;
        #pragma unroll
        for (int kk = 0; kk < BK; kk += 8) {
            float af[4][4], bf[8][2];
            #pragma unroll
            for (int mi = 0; mi < 4; mi++) {
                int r = wm + mi * 16 + gid;
                af[mi][0] = Ab[r * ASTR + kk + tig];
                af[mi][1] = Ab[(r + 8) * ASTR + kk + tig];
                af[mi][2] = Ab[r * ASTR + kk + tig + 4];
                af[mi][3] = Ab[(r + 8) * ASTR + kk + tig + 4];
            }
            #pragma unroll
            for (int ni = 0; ni < 8; ni++) {
                int c = wn + ni * 8 + gid;
                bf[ni][0] = Bb2[c * BSTR + kk + tig];
                bf[ni][1] = Bb2[c * BSTR + kk + tig + 4];
            }
            #pragma unroll
            for (int mi = 0; mi < 4; mi++)
                #pragma unroll
                for (int ni = 0; ni < 8; ni++)
                    mma_tf32(acc[mi][ni], af[mi], bf[ni]);
        }
    }

    #pragma unroll
    for (int mi = 0; mi < 4; mi++)
        #pragma unroll
        for (int ni = 0; ni < 8; ni++) {
            int r0 = bm + wm + mi * 16 + gid;
            int c0 = bn + wn + ni * 8 + tig * 2;
            #pragma unroll
            for (int j = 0; j < 4; j += 2) {
                int r = r0 + ((j >= 2) ? 8 : 0);
                float v0 = acc[mi][ni][j], v1 = acc[mi][ni][j + 1];
                if (bias) { v0 += bias[c0]; v1 += bias[c0 + 1]; }
                if (res) {
                    float2 rv = *(const float2*)&res[(long long)r * ldc + c0];
                    v0 += rv.x; v1 += rv.y;
                }
                if (GELU) {
                    v0 = 0.5f * v0 * (1.f + erff(v0 * 0.7071067811865476f));
                    v1 = 0.5f * v1 * (1.f + erff(v1 * 0.7071067811865476f));
                }
                *(float2*)&C[(long long)r * ldc + c0] = make_float2(v0, v1);
            }
        }
}

// =====================================================================
// Standard big GEMM (R12 winner wrapper)
// =====================================================================
template<bool GATE, bool GELU>
__global__ void __launch_bounds__(256)
gemm_big(const float* __restrict__ A0, const float* __restrict__ A1,
         const float* __restrict__ A2, int lda,
         const float* __restrict__ B, int ldb,
         float* __restrict__ C, int ldc, int K, const float* __restrict__ bias,
         const float* __restrict__ res)
{
    extern __shared__ float sm[];
    gemm_body<GATE, GELU>(A0, A1, A2, lda, B, ldb, C, ldc, K, bias, res,
                          blockIdx.y * 128, blockIdx.x * 256, sm);
}

// =====================================================================
// Dual GEMM: two independent NT projections in one launch (linear grid).
// blocks [0, NT0*MT0): matrix 0;  rest: matrix 1. Fills wave tails.
// =====================================================================
__global__ void __launch_bounds__(256)
gemm_dual(const float* __restrict__ A0, const float* __restrict__ B0,
          float* __restrict__ C0, int ldc0, const float* __restrict__ bias0,
          int NT0, int NB0,
          const float* __restrict__ A1p, const float* __restrict__ B1,
          float* __restrict__ C1, int ldc1, const float* __restrict__ bias1,
          int NT1)
{
    extern __shared__ float sm[];
    const int bid = blockIdx.x;
    if (bid < NB0) {
        gemm_body<false, false>(A0, nullptr, nullptr, 1024, B0, 1024,
                                C0, ldc0, 1024, bias0, nullptr,
                                (bid / NT0) * 128, (bid % NT0) * 256, sm);
    } else {
        const int t = bid - NB0;
        gemm_body<false, false>(A1p, nullptr, nullptr, 1024, B1, 1024,
                                C1, ldc1, 1024, bias1, nullptr,
                                (t / NT1) * 128, (t % NT1) * 256, sm);
    }
}

// =====================================================================
// Flash attention v2 (R12 winner): KT=32, single-sync pipeline.
// =====================================================================
template<int HD, int KV, int MINB, bool WML>
__global__ void __launch_bounds__(256, MINB)
flash2(const float* __restrict__ Qp, long long Qb, long long Qh, int ldq,
       const float* __restrict__ Kp, long long Kb, long long Kh, int ldk,
       const float* __restrict__ Vp, long long Vb, long long Vh, int ldv,
       float* __restrict__ Op, long long Ob, long long Oh, int ldo,
       float2* __restrict__ ML, int H, float scale)
{
    constexpr int BQ = 128, KT = 32;
    constexpr int QSTR = HD + 4;
    constexpr int KSTR = HD + 4;
    constexpr int VSTR = HD + 8;
    constexpr int PSTR = KT + 4;
    constexpr int QEL = BQ * QSTR, KEL = KT * KSTR, VEL = KT * VSTR;

    extern __shared__ float sm[];
    float* Qs = sm;
    float* Ks = Qs + QEL;
    float* Vs = Ks + 2 * KEL;
    float* Ps = Vs + 2 * VEL;

    const int bz = blockIdx.y;
    const int b = bz / H, h = bz % H;
    const int q0 = blockIdx.x * BQ;
    const float* Qg = Qp + (long long)b * Qb + (long long)h * Qh + (long long)q0 * ldq;
    const float* Kg = Kp + (long long)b * Kb + (long long)h * Kh;
    const float* Vg = Vp + (long long)b * Vb + (long long)h * Vh;
    float*       Og = Op + (long long)b * Ob + (long long)h * Oh + (long long)q0 * ldo;

    const int tid = threadIdx.x, warp = tid >> 5, lane = tid & 31;
    const int gid = lane >> 2, tig = lane & 3;
    const int w16 = warp * 16;

    auto loadQ = [&]() {
        #pragma unroll
        for (int i = tid; i < BQ * HD / 4; i += 256) {
            int r = i / (HD / 4), c = i % (HD / 4);
            cp_async16(&Qs[r * QSTR + c * 4], Qg + (long long)r * ldq + c * 4);
        }
    };
    auto loadK = [&](int buf, int t) {
        #pragma unroll
        for (int i = tid; i < KT * HD / 4; i += 256) {
            int r = i / (HD / 4), c = i % (HD / 4);
            cp_async16(&Ks[buf * KEL + r * KSTR + c * 4],
                       Kg + (long long)(t * KT + r) * ldk + c * 4);
        }
    };
    auto loadV = [&](int buf, int t) {
        #pragma unroll
        for (int i = tid; i < KT * HD / 4; i += 256) {
            int r = i / (HD / 4), c = i % (HD / 4);
            cp_async16(&Vs[buf * VEL + r * VSTR + c * 4],
                       Vg + (long long)(t * KT + r) * ldv + c * 4);
        }
    };

    constexpr int NO = HD / 8;
    constexpr int NS = KT / 8;
    float Ofr[NO][4] = {};
    float m0 = -1e30f, m1 = -1e30f, l0 = 0.f, l1 = 0.f;

    constexpr int T = KV / KT;
    loadQ(); loadK(0, 0); loadV(0, 0); cp_commit();

    for (int t = 0; t < T; t++) {
        cp_wait<0>();
        __syncthreads();
        if (t + 1 < T) {
            loadK((t + 1) & 1, t + 1);
            loadV((t + 1) & 1, t + 1);
            cp_commit();
        }

        const float* Kbuf = Ks + (t & 1) * KEL;
        float S[NS][4] = {};
        #pragma unroll
        for (int kk = 0; kk < HD; kk += 8) {
            float af[4];
            af[0] = Qs[(w16 + gid) * QSTR + kk + tig];
            af[1] = Qs[(w16 + 8 + gid) * QSTR + kk + tig];
            af[2] = Qs[(w16 + gid) * QSTR + kk + tig + 4];
            af[3] = Qs[(w16 + 8 + gid) * QSTR + kk + tig + 4];
            #pragma unroll
            for (int nt = 0; nt < NS; nt++) {
                float bf[2];
                bf[0] = Kbuf[(nt * 8 + gid) * KSTR + kk + tig];
                bf[1] = Kbuf[(nt * 8 + gid) * KSTR + kk + tig + 4];
                mma_tf32(S[nt], af, bf);
            }
        }

        float tm0 = -1e30f, tm1 = -1e30f;
        #pragma unroll
        for (int nt = 0; nt < NS; nt++) {
            S[nt][0] *= scale; S[nt][1] *= scale; S[nt][2] *= scale; S[nt][3] *= scale;
            tm0 = fmaxf(tm0, fmaxf(S[nt][0], S[nt][1]));
            tm1 = fmaxf(tm1, fmaxf(S[nt][2], S[nt][3]));
        }
        #pragma unroll
        for (int o = 1; o <= 2; o <<= 1) {
            tm0 = fmaxf(tm0, __shfl_xor_sync(0xffffffffu, tm0, o));
            tm1 = fmaxf(tm1, __shfl_xor_sync(0xffffffffu, tm1, o));
        }
        float mn0 = fmaxf(m0, tm0), mn1 = fmaxf(m1, tm1);
        float a0 = __expf(m0 - mn0), a1 = __expf(m1 - mn1);
        float ps0 = 0.f, ps1 = 0.f;
        #pragma unroll
        for (int nt = 0; nt < NS; nt++) {
            S[nt][0] = __expf(S[nt][0] - mn0); S[nt][1] = __expf(S[nt][1] - mn0);
            S[nt][2] = __expf(S[nt][2] - mn1); S[nt][3] = __expf(S[nt][3] - mn1);
            ps0 += S[nt][0] + S[nt][1];
            ps1 += S[nt][2] + S[nt][3];
        }
        #pragma unroll
        for (int o = 1; o <= 2; o <<= 1) {
            ps0 += __shfl_xor_sync(0xffffffffu, ps0, o);
            ps1 += __shfl_xor_sync(0xffffffffu, ps1, o);
        }
        l0 = l0 * a0 + ps0;  l1 = l1 * a1 + ps1;
        m0 = mn0;            m1 = mn1;
        #pragma unroll
        for (int no = 0; no < NO; no++) {
            Ofr[no][0] *= a0; Ofr[no][1] *= a0;
            Ofr[no][2] *= a1; Ofr[no][3] *= a1;
        }

        #pragma unroll
        for (int nt = 0; nt < NS; nt++) {
            *(float2*)&Ps[(w16 + gid) * PSTR + nt * 8 + tig * 2]     = make_float2(S[nt][0], S[nt][1]);
            *(float2*)&Ps[(w16 + 8 + gid) * PSTR + nt * 8 + tig * 2] = make_float2(S[nt][2], S[nt][3]);
        }
        __syncwarp();

        const float* Vbuf = Vs + (t & 1) * VEL;
        #pragma unroll
        for (int kk = 0; kk < KT; kk += 8) {
            float af[4];
            af[0] = Ps[(w16 + gid) * PSTR + kk + tig];
            af[1] = Ps[(w16 + 8 + gid) * PSTR + kk + tig];
            af[2] = Ps[(w16 + gid) * PSTR + kk + tig + 4];
            af[3] = Ps[(w16 + 8 + gid) * PSTR + kk + tig + 4];
            #pragma unroll
            for (int no = 0; no < NO; no++) {
                float bf[2];
                bf[0] = Vbuf[(kk + tig) * VSTR + no * 8 + gid];
                bf[1] = Vbuf[(kk + tig + 4) * VSTR + no * 8 + gid];
                mma_tf32(Ofr[no], af, bf);
            }
        }
    }

    float inv0 = 1.f / l0, inv1 = 1.f / l1;
    #pragma unroll
    for (int no = 0; no < NO; no++) {
        *(float2*)&Og[(long long)(w16 + gid) * ldo + no * 8 + tig * 2] =
            make_float2(Ofr[no][0] * inv0, Ofr[no][1] * inv0);
        *(float2*)&Og[(long long)(w16 + 8 + gid) * ldo + no * 8 + tig * 2] =
            make_float2(Ofr[no][2] * inv1, Ofr[no][3] * inv1);
    }
    if (WML && tig == 0) {
        long long mo = (long long)bz * 512 + q0;
        ML[mo + w16 + gid]     = make_float2(m0, inv0);
        ML[mo + w16 + 8 + gid] = make_float2(m1, inv1);
    }
}

// =====================================================================
// Cross attn-weights mean (R15 winner): q-tile 128 x s-tile 64,
// double-buffered, 102KB smem; forked to side stream for overlap.
// =====================================================================
__global__ void __launch_bounds__(256)
cross_mean(const float* __restrict__ Q, const float* __restrict__ K,
           const float2* __restrict__ ML, float* __restrict__ out)
{
    constexpr int STR = 68;
    constexpr int QEL = 128 * STR;
    constexpr int KEL = 64 * STR;
    extern __shared__ float sm[];
    float* Qs = sm;
    float* Ks = sm + 2 * QEL;

    const int b = blockIdx.z, s0 = blockIdx.y * 64, q0 = blockIdx.x * 128;
    const float* Qg = Q + (long long)b * 524288 + (long long)q0 * 1024;
    const float* Kg = K + (long long)b * 2097152 + (long long)s0 * 2048;

    const int tid = threadIdx.x, warp = tid >> 5, lane = tid & 31;
    const int gid = lane >> 2, tig = lane & 3;
    const int w16 = warp * 16;

    auto loadQ = [&](int buf, int h) {
        #pragma unroll
        for (int i = tid; i < 2048; i += 256) {
            int r = i >> 4, c = i & 15;
            cp_async16(&Qs[buf * QEL + r * STR + c * 4],
                       Qg + (long long)r * 1024 + h * 64 + c * 4);
        }
    };
    auto loadK = [&](int buf, int h) {
        #pragma unroll
        for (int i = tid; i < 1024; i += 256) {
            int r = i >> 4, c = i & 15;
            cp_async16(&Ks[buf * KEL + r * STR + c * 4],
                       Kg + (long long)r * 2048 + h * 64 + c * 4);
        }
    };

    float acc[8][4] = {};
    loadQ(0, 0); loadK(0, 0); cp_commit();

    for (int h = 0; h < 16; h++) {
        const int buf = h & 1;
        cp_wait<0>();
        __syncthreads();
        if (h + 1 < 16) { loadQ(buf ^ 1, h + 1); loadK(buf ^ 1, h + 1); cp_commit(); }

        float2 mlA = ML[(long long)(b * 16 + h) * 512 + q0 + w16 + gid];
        float2 mlB = ML[(long long)(b * 16 + h) * 512 + q0 + w16 + 8 + gid];
        const float* Qb = Qs + buf * QEL;
        const float* Kb = Ks + buf * KEL;

        float S[8][4] = {};
        #pragma unroll
        for (int kk = 0; kk < 64; kk += 8) {
            float af[4];
            af[0] = Qb[(w16 + gid) * STR + kk + tig];
            af[1] = Qb[(w16 + 8 + gid) * STR + kk + tig];
            af[2] = Qb[(w16 + gid) * STR + kk + tig + 4];
            af[3] = Qb[(w16 + 8 + gid) * STR + kk + tig + 4];
            #pragma unroll
            for (int nt = 0; nt < 8; nt++) {
                float bf[2];
                bf[0] = Kb[(nt * 8 + gid) * STR + kk + tig];
                bf[1] = Kb[(nt * 8 + gid) * STR + kk + tig + 4];
                mma_tf32(S[nt], af, bf);
            }
        }
        #pragma unroll
        for (int nt = 0; nt < 8; nt++) {
            acc[nt][0] += __expf(fmaf(S[nt][0], 0.125f, -mlA.x)) * mlA.y;
            acc[nt][1] += __expf(fmaf(S[nt][1], 0.125f, -mlA.x)) * mlA.y;
            acc[nt][2] += __expf(fmaf(S[nt][2], 0.125f, -mlB.x)) * mlB.y;
            acc[nt][3] += __expf(fmaf(S[nt][3], 0.125f, -mlB.x)) * mlB.y;
        }
    }

    const long long obase = (long long)b * 524288 + (long long)q0 * 1024 + s0;
    #pragma unroll
    for (int nt = 0; nt < 8; nt++) {
        *(float2*)&out[obase + (long long)(w16 + gid) * 1024 + nt * 8 + tig * 2] =
            make_float2(acc[nt][0] * 0.0625f, acc[nt][1] * 0.0625f);
        *(float2*)&out[obase + (long long)(w16 + 8 + gid) * 1024 + nt * 8 + tig * 2] =
            make_float2(acc[nt][2] * 0.0625f, acc[nt][3] * 0.0625f);
    }
}

// ---------------- LayerNorm (row = 1024), input already has residual ----------------
__global__ void ln4(const float4* __restrict__ x,
                    const float4* __restrict__ g, const float4* __restrict__ bt,
                    float4* __restrict__ out)
{
    const int row = blockIdx.x, tid = threadIdx.x;
    const long long base = (long long)row * 256;
    __shared__ float ss[8], sq[8];
    __shared__ float smu, srs;

    float4 v = x[base + tid];
    float s = v.x + v.y + v.z + v.w;
    float q = v.x * v.x + v.y * v.y + v.z * v.z + v.w * v.w;
    #pragma unroll
    for (int o = 16; o; o >>= 1) {
        s += __shfl_xor_sync(0xffffffffu, s, o);
        q += __shfl_xor_sync(0xffffffffu, q, o);
    }
    const int warp = tid >> 5;
    if ((tid & 31) == 0) { ss[warp] = s; sq[warp] = q; }
    __syncthreads();
    if (tid == 0) {
        float S = 0.f, Q = 0.f;
        #pragma unroll
        for (int i = 0; i < 8; i++) { S += ss[i]; Q += sq[i]; }
        float mu  = S * (1.f / 1024.f);
        float var = Q * (1.f / 1024.f) - mu * mu;
        smu = mu;
        srs = rsqrtf(var + 1e-5f);
    }
    __syncthreads();
    float mu = smu, rs = srs;
    float4 gv = g[tid], bv = bt[tid];
    out[base + tid] = make_float4((v.x - mu) * rs * gv.x + bv.x,
                                  (v.y - mu) * rs * gv.y + bv.y,
                                  (v.z - mu) * rs * gv.z + bv.z,
                                  (v.w - mu) * rs * gv.w + bv.w);
}

// ---------------- gate logits + softmax(3) + combine, float4 ----------------
__global__ void gate_combine4(const float4* __restrict__ h,
                              const float4* __restrict__ w2, const float* __restrict__ b2,
                              const float4* __restrict__ s0, const float4* __restrict__ s1,
                              const float4* __restrict__ s2, float4* __restrict__ out)
{
    const int row = blockIdx.x, tid = threadIdx.x;
    const long long base = (long long)row * 256;
    __shared__ float r0[8], r1[8], r2[8];
    __shared__ float w[3];

    float4 hv = h[base + tid];
    float4 wa = w2[tid], wb = w2[256 + tid], wc = w2[512 + tid];
    float p0 = hv.x * wa.x + hv.y * wa.y + hv.z * wa.z + hv.w * wa.w;
    float p1 = hv.x * wb.x + hv.y * wb.y + hv.z * wb.z + hv.w * wb.w;
    float p2 = hv.x * wc.x + hv.y * wc.y + hv.z * wc.z + hv.w * wc.w;
    #pragma unroll
    for (int o = 16; o; o >>= 1) {
        p0 += __shfl_xor_sync(0xffffffffu, p0, o);
        p1 += __shfl_xor_sync(0xffffffffu, p1, o);
        p2 += __shfl_xor_sync(0xffffffffu, p2, o);
    }
    const int warp = tid >> 5;
    if ((tid & 31) == 0) { r0[warp] = p0; r1[warp] = p1; r2[warp] = p2; }
    __syncthreads();
    if (tid == 0) {
        float l0 = b2[0], l1 = b2[1], l2 = b2[2];
        #pragma unroll
        for (int i = 0; i < 8; i++) { l0 += r0[i]; l1 += r1[i]; l2 += r2[i]; }
        float m  = fmaxf(l0, fmaxf(l1, l2));
        float e0 = __expf(l0 - m), e1 = __expf(l1 - m), e2 = __expf(l2 - m);
        float inv = 1.f / (e0 + e1 + e2);
        w[0] = e0 * inv; w[1] = e1 * inv; w[2] = e2 * inv;
    }
    __syncthreads();
    float w0 = w[0], w1 = w[1], w2v = w[2];
    float4 a = s0[base + tid], b = s1[base + tid], c = s2[base + tid];
    out[base + tid] = make_float4(w0 * a.x + w1 * b.x + w2v * c.x,
                                  w0 * a.y + w1 * b.y + w2v * c.y,
                                  w0 * a.z + w1 * b.z + w2v * c.z,
                                  w0 * a.w + w1 * b.w + w2v * c.w);
}

// ---------------- launch ----------------
extern "C" void kernel_launch(void* const* d_in, const int* in_sizes, int n_in,
                              void* d_out, int out_size)
{
    (void)in_sizes; (void)n_in; (void)out_size;

    const float* proto = (const float*)d_in[0];
    const float* img   = (const float*)d_in[1];
    const float* cwi   = (const float*)d_in[2];
    const float* cbi   = (const float*)d_in[3];
    const float* cwo   = (const float*)d_in[4];
    const float* cbo   = (const float*)d_in[5];
    const float* swi   = (const float*)d_in[6];
    const float* sbi   = (const float*)d_in[7];
    const float* swo   = (const float*)d_in[8];
    const float* sbo   = (const float*)d_in[9];
    const float* lwi   = (const float*)d_in[10];
    const float* lbi   = (const float*)d_in[11];
    const float* lwo   = (const float*)d_in[12];
    const float* lbo   = (const float*)d_in[13];
    const float* n1g   = (const float*)d_in[14];
    const float* n1b   = (const float*)d_in[15];
    const float* n2g   = (const float*)d_in[16];
    const float* n2b   = (const float*)d_in[17];
    const float* n3g   = (const float*)d_in[18];
    const float* n3b   = (const float*)d_in[19];
    const float* gw1   = (const float*)d_in[20];
    const float* gb1   = (const float*)d_in[21];
    const float* gw2   = (const float*)d_in[22];
    const float* gb2   = (const float*)d_in[23];

    float* out_upd  = (float*)d_out;
    float* out_attn = (float*)d_out + 8388608;

    float *q, *kv, *qkv, *ob, *rw, *cr, *se, *li, *hb;
    float2* ml;
    cudaGetSymbolAddress((void**)&q,   g_q);
    cudaGetSymbolAddress((void**)&kv,  g_kv);
    cudaGetSymbolAddress((void**)&qkv, g_qkv);
    cudaGetSymbolAddress((void**)&ml,  g_ml);
    cudaGetSymbolAddress((void**)&ob,  g_ob);
    cudaGetSymbolAddress((void**)&rw,  g_rw);
    cudaGetSymbolAddress((void**)&cr,  g_cross);
    cudaGetSymbolAddress((void**)&se,  g_selfo);
    cudaGetSymbolAddress((void**)&li,  g_light);
    cudaGetSymbolAddress((void**)&hb,  g_hb);

    constexpr size_t SM_BIG  = (2 * 128 * 68 + 2 * 256 * 68) * 4;    // 208896 (BK=64)
    constexpr size_t SM_F64  = (128 * 68 + 2 * 32 * 68 + 2 * 32 * 72 + 128 * 36) * 4;
    constexpr size_t SM_F128 = (128 * 132 + 2 * 32 * 132 + 2 * 32 * 136 + 128 * 36) * 4;
    constexpr size_t SM_CM   = (2 * 128 * 68 + 2 * 64 * 68) * 4;     // 104448

    cudaFuncSetAttribute((const void*)gemm_big<false,false>,
                         cudaFuncAttributeMaxDynamicSharedMemorySize, SM_BIG);
    cudaFuncSetAttribute((const void*)gemm_big<true,true>,
                         cudaFuncAttributeMaxDynamicSharedMemorySize, SM_BIG);
    cudaFuncSetAttribute((const void*)gemm_dual,
                         cudaFuncAttributeMaxDynamicSharedMemorySize, SM_BIG);
    cudaFuncSetAttribute((const void*)flash2<64,1024,2,true>,
                         cudaFuncAttributeMaxDynamicSharedMemorySize, SM_F64);
    cudaFuncSetAttribute((const void*)flash2<64,512,2,false>,
                         cudaFuncAttributeMaxDynamicSharedMemorySize, SM_F64);
    cudaFuncSetAttribute((const void*)flash2<128,512,1,false>,
                         cudaFuncAttributeMaxDynamicSharedMemorySize, SM_F128);
    cudaFuncSetAttribute((const void*)cross_mean,
                         cudaFuncAttributeMaxDynamicSharedMemorySize, SM_CM);

    // Side stream + events for the cross_mean fork (created per call;
    // not destroyed — destroying during graph capture invalidates it).
    cudaStream_t s2;
    cudaStreamCreateWithFlags(&s2, cudaStreamNonBlocking);
    cudaEvent_t evF, evJ;
    cudaEventCreateWithFlags(&evF, cudaEventDisableTiming);
    cudaEventCreateWithFlags(&evJ, cudaEventDisableTiming);

    // ============ cross attention (H=16, hd=64, kv=1024) — flash ============
    // Q-proj (256 tiles) + KV-proj (1024 tiles) fused into one 1280-block launch
    gemm_dual<<<1280,256,SM_BIG>>>(
        proto, cwi,          q,  1024, cbi,        4, 256,
        img,   cwi+1048576,  kv, 2048, cbi+1024,   8);
    flash2<64,1024,2,true><<<dim3(4,256),256,SM_F64>>>(
        q,       524288LL,64LL,1024,
        kv,      2097152LL,64LL,2048,
        kv+1024, 2097152LL,64LL,2048,
        ob, 524288LL,64LL,1024,
        ml, 16, 0.125f);

    // fork: cross_mean on side stream (co-residency-sized: 102KB smem)
    cudaEventRecord(evF, 0);
    cudaStreamWaitEvent(s2, evF, 0);
    cross_mean<<<dim3(4,16,16),256,SM_CM,s2>>>(q, kv, ml, out_attn);
    cudaEventRecord(evJ, s2);

    gemm_big<false,false><<<dim3(4,64),256,SM_BIG>>>(
        ob,nullptr,nullptr,1024,  cwo,1024,  rw,1024,  1024, cbo, proto);
    ln4<<<8192,256>>>((const float4*)rw,(const float4*)n1g,(const float4*)n1b,(float4*)cr);

    // ============ self attention (H=16, hd=64, kv=512) — flash ============
    gemm_big<false,false><<<dim3(12,64),256,SM_BIG>>>(
        cr,nullptr,nullptr,1024,  swi,1024,  qkv,3072,  1024, sbi, nullptr);
    flash2<64,512,2,false><<<dim3(4,256),256,SM_F64>>>(
        qkv,      1572864LL,64LL,3072,
        qkv+1024, 1572864LL,64LL,3072,
        qkv+2048, 1572864LL,64LL,3072,
        ob, 524288LL,64LL,1024,
        nullptr, 16, 0.125f);
    gemm_big<false,false><<<dim3(4,64),256,SM_BIG>>>(
        ob,nullptr,nullptr,1024,  swo,1024,  rw,1024,  1024, sbo, cr);
    ln4<<<8192,256>>>((const float4*)rw,(const float4*)n2g,(const float4*)n2b,(float4*)se);

    // ============ light attention (H=8, hd=128, kv=512) — flash ============
    gemm_big<false,false><<<dim3(12,64),256,SM_BIG>>>(
        se,nullptr,nullptr,1024,  lwi,1024,  qkv,3072,  1024, lbi, nullptr);
    flash2<128,512,1,false><<<dim3(4,128),256,SM_F128>>>(
        qkv,      1572864LL,128LL,3072,
        qkv+1024, 1572864LL,128LL,3072,
        qkv+2048, 1572864LL,128LL,3072,
        ob, 524288LL,128LL,1024,
        nullptr, 8, 0.08838834764831845f);
    gemm_big<false,false><<<dim3(4,64),256,SM_BIG>>>(
        ob,nullptr,nullptr,1024,  lwo,1024,  rw,1024,  1024, lbo, se);
    ln4<<<8192,256>>>((const float4*)rw,(const float4*)n3g,(const float4*)n3b,(float4*)li);

    // ============ gate MLP (single K=3072 GEMM, GELU fused) ============
    gemm_big<true,true><<<dim3(4,64),256,SM_BIG>>>(
        cr,se,li,1024,  gw1,3072,  hb,1024,  3072, gb1, nullptr);

    // join side stream before the final kernel
    cudaStreamWaitEvent(0, evJ, 0);

    // ============ gate softmax(3) + combine ============
    gate_combine4<<<8192,256>>>((const float4*)hb,(const float4*)gw2,gb2,
                                (const float4*)cr,(const float4*)se,(const float4*)li,
                                (float4*)out_upd);
}

// round 17
// speedup vs baseline: 1.0077x; 1.0077x over previous
#include <cuda_runtime.h>
#include <math.h>

// ---------------- problem constants ----------------
// B=16, P=512, S=1024, D=1024, H_FULL=16 (hd=64), H_LIGHT=8 (hd=128)

// ---------------- device scratch ----------------
__device__ float  g_q     [8192u  * 1024u];
__device__ float  g_kv    [16384u * 2048u];
__device__ float  g_qkv   [8192u  * 3072u];
__device__ float2 g_ml    [16u * 16u * 512u];   // cross (m, 1/l) per [b][h][p]
__device__ float  g_ob    [8192u  * 1024u];
__device__ float  g_rw    [8192u  * 1024u];
__device__ float  g_cross [8192u  * 1024u];
__device__ float  g_selfo [8192u  * 1024u];
__device__ float  g_light [8192u  * 1024u];
__device__ float  g_hb    [8192u  * 1024u];

// ---------------- async copy helpers ----------------
__device__ __forceinline__ void cp_async16(void* smem, const void* gmem) {
    unsigned s = (unsigned)__cvta_generic_to_shared(smem);
    asm volatile("cp.async.cg.shared.global [%0], [%1], 16;\n" :: "r"(s), "l"(gmem));
}
__device__ __forceinline__ void cp_commit() { asm volatile("cp.async.commit_group;\n"); }
template<int N> __device__ __forceinline__ void cp_wait() {
    asm volatile("cp.async.wait_group %0;\n" :: "n"(N));
}

__device__ __forceinline__ void mma_tf32(float* d, const float* a, const float* b) {
    const unsigned* A  = reinterpret_cast<const unsigned*>(a);
    const unsigned* Bv = reinterpret_cast<const unsigned*>(b);
    asm volatile(
        "mma.sync.aligned.m16n8k8.row.col.f32.tf32.tf32.f32 "
        "{%0,%1,%2,%3}, {%4,%5,%6,%7}, {%8,%9}, {%0,%1,%2,%3};"
        : "+f"(d[0]), "+f"(d[1]), "+f"(d[2]), "+f"(d[3])
        : "r"(A[0]), "r"(A[1]), "r"(A[2]), "r"(A[3]), "r"(Bv[0]), "r"(Bv[1]));
}

// =====================================================================
// Big-tile projection GEMM (R12 winner): single-sync pipeline, BK=64.
// C = A @ B^T + bias (+res). BM=128 BN=256, warp tile 64x64.
// =====================================================================
template<bool GATE, bool GELU>
__global__ void __launch_bounds__(256)
gemm_big(const float* __restrict__ A0, const float* __restrict__ A1,
         const float* __restrict__ A2, int lda,
         const float* __restrict__ B, int ldb,
         float* __restrict__ C, int ldc, int K, const float* __restrict__ bias,
         const float* __restrict__ res)
{
    constexpr int BM = 128, BN = 256, BK = 64;
    constexpr int ASTR = BK + 4, BSTR = BK + 4;
    constexpr int AEL = BM * ASTR, BEL = BN * BSTR;

    extern __shared__ float sm[];
    float* As = sm;
    float* Bs = sm + 2 * AEL;

    const int bm = blockIdx.y * BM, bn = blockIdx.x * BN;
    const int tid = threadIdx.x, warp = tid >> 5, lane = tid & 31;
    const int gid = lane >> 2, tig = lane & 3;
    const int wm = (warp & 1) * 64, wn = (warp >> 1) * 64;

    float acc[4][8][4] = {};

    auto loadA = [&](int buf, int k0) {
        const float* Ab;
        if (GATE) {
            Ab = (k0 < 1024) ? (A0 + k0)
               : (k0 < 2048) ? (A1 + (k0 - 1024))
                             : (A2 + (k0 - 2048));
        } else Ab = A0 + k0;
        #pragma unroll
        for (int i = tid; i < BM * 16; i += 256) {
            int r = i / 16, c = i % 16;
            cp_async16(&As[buf * AEL + r * ASTR + c * 4],
                       Ab + (long long)(bm + r) * lda + c * 4);
        }
    };
    auto loadB = [&](int buf, int k0) {
        #pragma unroll
        for (int i = tid; i < BN * 16; i += 256) {
            int r = i / 16, c = i % 16;
            cp_async16(&Bs[buf * BEL + r * BSTR + c * 4],
                       B + (long long)(bn + r) * ldb + k0 + c * 4);
        }
    };

    const int T = K / BK;
    loadA(0, 0); loadB(0, 0); cp_commit();
    for (int t = 0; t < T; t++) {
        cp_wait<0>();
        __syncthreads();
        if (t + 1 < T) {
            loadA((t + 1) & 1, (t + 1) * BK);
            loadB((t + 1) & 1, (t + 1) * BK);
            cp_commit();
        }
        const float* Ab  = As + (t & 1) * AEL;
        const float* Bb2 = Bs + (t & 1) * BEL;
        #pragma unroll
        for (int kk = 0; kk < BK; kk += 8) {
            float af[4][4], bf[8][2];
            #pragma unroll
            for (int mi = 0; mi < 4; mi++) {
                int r = wm + mi * 16 + gid;
                af[mi][0] = Ab[r * ASTR + kk + tig];
                af[mi][1] = Ab[(r + 8) * ASTR + kk + tig];
                af[mi][2] = Ab[r * ASTR + kk + tig + 4];
                af[mi][3] = Ab[(r + 8) * ASTR + kk + tig + 4];
            }
            #pragma unroll
            for (int ni = 0; ni < 8; ni++) {
                int c = wn + ni * 8 + gid;
                bf[ni][0] = Bb2[c * BSTR + kk + tig];
                bf[ni][1] = Bb2[c * BSTR + kk + tig + 4];
            }
            #pragma unroll
            for (int mi = 0; mi < 4; mi++)
                #pragma unroll
                for (int ni = 0; ni < 8; ni++)
                    mma_tf32(acc[mi][ni], af[mi], bf[ni]);
        }
    }

    #pragma unroll
    for (int mi = 0; mi < 4; mi++)
        #pragma unroll
        for (int ni = 0; ni < 8; ni++) {
            int r0 = bm + wm + mi * 16 + gid;
            int c0 = bn + wn + ni * 8 + tig * 2;
            #pragma unroll
            for (int j = 0; j < 4; j += 2) {
                int r = r0 + ((j >= 2) ? 8 : 0);
                float v0 = acc[mi][ni][j], v1 = acc[mi][ni][j + 1];
                if (bias) { v0 += bias[c0]; v1 += bias[c0 + 1]; }
                if (res) {
                    float2 rv = *(const float2*)&res[(long long)r * ldc + c0];
                    v0 += rv.x; v1 += rv.y;
                }
                if (GELU) {
                    v0 = 0.5f * v0 * (1.f + erff(v0 * 0.7071067811865476f));
                    v1 = 0.5f * v1 * (1.f + erff(v1 * 0.7071067811865476f));
                }
                *(float2*)&C[(long long)r * ldc + c0] = make_float2(v0, v1);
            }
        }
}

// =====================================================================
// Flash attention v2 (R12 winner): KT=32, single-sync pipeline.
// =====================================================================
template<int HD, int KV, int MINB, bool WML>
__global__ void __launch_bounds__(256, MINB)
flash2(const float* __restrict__ Qp, long long Qb, long long Qh, int ldq,
       const float* __restrict__ Kp, long long Kb, long long Kh, int ldk,
       const float* __restrict__ Vp, long long Vb, long long Vh, int ldv,
       float* __restrict__ Op, long long Ob, long long Oh, int ldo,
       float2* __restrict__ ML, int H, float scale)
{
    constexpr int BQ = 128, KT = 32;
    constexpr int QSTR = HD + 4;
    constexpr int KSTR = HD + 4;
    constexpr int VSTR = HD + 8;
    constexpr int PSTR = KT + 4;
    constexpr int QEL = BQ * QSTR, KEL = KT * KSTR, VEL = KT * VSTR;

    extern __shared__ float sm[];
    float* Qs = sm;
    float* Ks = Qs + QEL;
    float* Vs = Ks + 2 * KEL;
    float* Ps = Vs + 2 * VEL;

    const int bz = blockIdx.y;
    const int b = bz / H, h = bz % H;
    const int q0 = blockIdx.x * BQ;
    const float* Qg = Qp + (long long)b * Qb + (long long)h * Qh + (long long)q0 * ldq;
    const float* Kg = Kp + (long long)b * Kb + (long long)h * Kh;
    const float* Vg = Vp + (long long)b * Vb + (long long)h * Vh;
    float*       Og = Op + (long long)b * Ob + (long long)h * Oh + (long long)q0 * ldo;

    const int tid = threadIdx.x, warp = tid >> 5, lane = tid & 31;
    const int gid = lane >> 2, tig = lane & 3;
    const int w16 = warp * 16;

    auto loadQ = [&]() {
        #pragma unroll
        for (int i = tid; i < BQ * HD / 4; i += 256) {
            int r = i / (HD / 4), c = i % (HD / 4);
            cp_async16(&Qs[r * QSTR + c * 4], Qg + (long long)r * ldq + c * 4);
        }
    };
    auto loadK = [&](int buf, int t) {
        #pragma unroll
        for (int i = tid; i < KT * HD / 4; i += 256) {
            int r = i / (HD / 4), c = i % (HD / 4);
            cp_async16(&Ks[buf * KEL + r * KSTR + c * 4],
                       Kg + (long long)(t * KT + r) * ldk + c * 4);
        }
    };
    auto loadV = [&](int buf, int t) {
        #pragma unroll
        for (int i = tid; i < KT * HD / 4; i += 256) {
            int r = i / (HD / 4), c = i % (HD / 4);
            cp_async16(&Vs[buf * VEL + r * VSTR + c * 4],
                       Vg + (long long)(t * KT + r) * ldv + c * 4);
        }
    };

    constexpr int NO = HD / 8;
    constexpr int NS = KT / 8;
    float Ofr[NO][4] = {};
    float m0 = -1e30f, m1 = -1e30f, l0 = 0.f, l1 = 0.f;

    constexpr int T = KV / KT;
    loadQ(); loadK(0, 0); loadV(0, 0); cp_commit();

    for (int t = 0; t < T; t++) {
        cp_wait<0>();
        __syncthreads();
        if (t + 1 < T) {
            loadK((t + 1) & 1, t + 1);
            loadV((t + 1) & 1, t + 1);
            cp_commit();
        }

        const float* Kbuf = Ks + (t & 1) * KEL;
        float S[NS][4] = {};
        #pragma unroll
        for (int kk = 0; kk < HD; kk += 8) {
            float af[4];
            af[0] = Qs[(w16 + gid) * QSTR + kk + tig];
            af[1] = Qs[(w16 + 8 + gid) * QSTR + kk + tig];
            af[2] = Qs[(w16 + gid) * QSTR + kk + tig + 4];
            af[3] = Qs[(w16 + 8 + gid) * QSTR + kk + tig + 4];
            #pragma unroll
            for (int nt = 0; nt < NS; nt++) {
                float bf[2];
                bf[0] = Kbuf[(nt * 8 + gid) * KSTR + kk + tig];
                bf[1] = Kbuf[(nt * 8 + gid) * KSTR + kk + tig + 4];
                mma_tf32(S[nt], af, bf);
            }
        }

        float tm0 = -1e30f, tm1 = -1e30f;
        #pragma unroll
        for (int nt = 0; nt < NS; nt++) {
            S[nt][0] *= scale; S[nt][1] *= scale; S[nt][2] *= scale; S[nt][3] *= scale;
            tm0 = fmaxf(tm0, fmaxf(S[nt][0], S[nt][1]));
            tm1 = fmaxf(tm1, fmaxf(S[nt][2], S[nt][3]));
        }
        #pragma unroll
        for (int o = 1; o <= 2; o <<= 1) {
            tm0 = fmaxf(tm0, __shfl_xor_sync(0xffffffffu, tm0, o));
            tm1 = fmaxf(tm1, __shfl_xor_sync(0xffffffffu, tm1, o));
        }
        float mn0 = fmaxf(m0, tm0), mn1 = fmaxf(m1, tm1);
        float a0 = __expf(m0 - mn0), a1 = __expf(m1 - mn1);
        float ps0 = 0.f, ps1 = 0.f;
        #pragma unroll
        for (int nt = 0; nt < NS; nt++) {
            S[nt][0] = __expf(S[nt][0] - mn0); S[nt][1] = __expf(S[nt][1] - mn0);
            S[nt][2] = __expf(S[nt][2] - mn1); S[nt][3] = __expf(S[nt][3] - mn1);
            ps0 += S[nt][0] + S[nt][1];
            ps1 += S[nt][2] + S[nt][3];
        }
        #pragma unroll
        for (int o = 1; o <= 2; o <<= 1) {
            ps0 += __shfl_xor_sync(0xffffffffu, ps0, o);
            ps1 += __shfl_xor_sync(0xffffffffu, ps1, o);
        }
        l0 = l0 * a0 + ps0;  l1 = l1 * a1 + ps1;
        m0 = mn0;            m1 = mn1;
        #pragma unroll
        for (int no = 0; no < NO; no++) {
            Ofr[no][0] *= a0; Ofr[no][1] *= a0;
            Ofr[no][2] *= a1; Ofr[no][3] *= a1;
        }

        #pragma unroll
        for (int nt = 0; nt < NS; nt++) {
            *(float2*)&Ps[(w16 + gid) * PSTR + nt * 8 + tig * 2]     = make_float2(S[nt][0], S[nt][1]);
            *(float2*)&Ps[(w16 + 8 + gid) * PSTR + nt * 8 + tig * 2] = make_float2(S[nt][2], S[nt][3]);
        }
        __syncwarp();

        const float* Vbuf = Vs + (t & 1) * VEL;
        #pragma unroll
        for (int kk = 0; kk < KT; kk += 8) {
            float af[4];
            af[0] = Ps[(w16 + gid) * PSTR + kk + tig];
            af[1] = Ps[(w16 + 8 + gid) * PSTR + kk + tig];
            af[2] = Ps[(w16 + gid) * PSTR + kk + tig + 4];
            af[3] = Ps[(w16 + 8 + gid) * PSTR + kk + tig + 4];
            #pragma unroll
            for (int no = 0; no < NO; no++) {
                float bf[2];
                bf[0] = Vbuf[(kk + tig) * VSTR + no * 8 + gid];
                bf[1] = Vbuf[(kk + tig + 4) * VSTR + no * 8 + gid];
                mma_tf32(Ofr[no], af, bf);
            }
        }
    }

    float inv0 = 1.f / l0, inv1 = 1.f / l1;
    #pragma unroll
    for (int no = 0; no < NO; no++) {
        *(float2*)&Og[(long long)(w16 + gid) * ldo + no * 8 + tig * 2] =
            make_float2(Ofr[no][0] * inv0, Ofr[no][1] * inv0);
        *(float2*)&Og[(long long)(w16 + 8 + gid) * ldo + no * 8 + tig * 2] =
            make_float2(Ofr[no][2] * inv1, Ofr[no][3] * inv1);
    }
    if (WML && tig == 0) {
        long long mo = (long long)bz * 512 + q0;
        ML[mo + w16 + gid]     = make_float2(m0, inv0);
        ML[mo + w16 + 8 + gid] = make_float2(m1, inv1);
    }
}

// =====================================================================
// Cross attn-weights mean (R15 winner): q-tile 128 x s-tile 64,
// double-buffered, 102KB smem; forked to side stream for overlap.
// =====================================================================
__global__ void __launch_bounds__(256)
cross_mean(const float* __restrict__ Q, const float* __restrict__ K,
           const float2* __restrict__ ML, float* __restrict__ out)
{
    constexpr int STR = 68;
    constexpr int QEL = 128 * STR;
    constexpr int KEL = 64 * STR;
    extern __shared__ float sm[];
    float* Qs = sm;
    float* Ks = sm + 2 * QEL;

    const int b = blockIdx.z, s0 = blockIdx.y * 64, q0 = blockIdx.x * 128;
    const float* Qg = Q + (long long)b * 524288 + (long long)q0 * 1024;
    const float* Kg = K + (long long)b * 2097152 + (long long)s0 * 2048;

    const int tid = threadIdx.x, warp = tid >> 5, lane = tid & 31;
    const int gid = lane >> 2, tig = lane & 3;
    const int w16 = warp * 16;

    auto loadQ = [&](int buf, int h) {
        #pragma unroll
        for (int i = tid; i < 2048; i += 256) {
            int r = i >> 4, c = i & 15;
            cp_async16(&Qs[buf * QEL + r * STR + c * 4],
                       Qg + (long long)r * 1024 + h * 64 + c * 4);
        }
    };
    auto loadK = [&](int buf, int h) {
        #pragma unroll
        for (int i = tid; i < 1024; i += 256) {
            int r = i >> 4, c = i & 15;
            cp_async16(&Ks[buf * KEL + r * STR + c * 4],
                       Kg + (long long)r * 2048 + h * 64 + c * 4);
        }
    };

    float acc[8][4] = {};
    loadQ(0, 0); loadK(0, 0); cp_commit();

    for (int h = 0; h < 16; h++) {
        const int buf = h & 1;
        cp_wait<0>();
        __syncthreads();
        if (h + 1 < 16) { loadQ(buf ^ 1, h + 1); loadK(buf ^ 1, h + 1); cp_commit(); }

        float2 mlA = ML[(long long)(b * 16 + h) * 512 + q0 + w16 + gid];
        float2 mlB = ML[(long long)(b * 16 + h) * 512 + q0 + w16 + 8 + gid];
        const float* Qb = Qs + buf * QEL;
        const float* Kb = Ks + buf * KEL;

        float S[8][4] = {};
        #pragma unroll
        for (int kk = 0; kk < 64; kk += 8) {
            float af[4];
            af[0] = Qb[(w16 + gid) * STR + kk + tig];
            af[1] = Qb[(w16 + 8 + gid) * STR + kk + tig];
            af[2] = Qb[(w16 + gid) * STR + kk + tig + 4];
            af[3] = Qb[(w16 + 8 + gid) * STR + kk + tig + 4];
            #pragma unroll
            for (int nt = 0; nt < 8; nt++) {
                float bf[2];
                bf[0] = Kb[(nt * 8 + gid) * STR + kk + tig];
                bf[1] = Kb[(nt * 8 + gid) * STR + kk + tig + 4];
                mma_tf32(S[nt], af, bf);
            }
        }
        #pragma unroll
        for (int nt = 0; nt < 8; nt++) {
            acc[nt][0] += __expf(fmaf(S[nt][0], 0.125f, -mlA.x)) * mlA.y;
            acc[nt][1] += __expf(fmaf(S[nt][1], 0.125f, -mlA.x)) * mlA.y;
            acc[nt][2] += __expf(fmaf(S[nt][2], 0.125f, -mlB.x)) * mlB.y;
            acc[nt][3] += __expf(fmaf(S[nt][3], 0.125f, -mlB.x)) * mlB.y;
        }
    }

    const long long obase = (long long)b * 524288 + (long long)q0 * 1024 + s0;
    #pragma unroll
    for (int nt = 0; nt < 8; nt++) {
        *(float2*)&out[obase + (long long)(w16 + gid) * 1024 + nt * 8 + tig * 2] =
            make_float2(acc[nt][0] * 0.0625f, acc[nt][1] * 0.0625f);
        *(float2*)&out[obase + (long long)(w16 + 8 + gid) * 1024 + nt * 8 + tig * 2] =
            make_float2(acc[nt][2] * 0.0625f, acc[nt][3] * 0.0625f);
    }
}

// ---------------- LayerNorm (row = 1024), input already has residual ----------------
__global__ void ln4(const float4* __restrict__ x,
                    const float4* __restrict__ g, const float4* __restrict__ bt,
                    float4* __restrict__ out)
{
    const int row = blockIdx.x, tid = threadIdx.x;
    const long long base = (long long)row * 256;
    __shared__ float ss[8], sq[8];
    __shared__ float smu, srs;

    float4 v = x[base + tid];
    float s = v.x + v.y + v.z + v.w;
    float q = v.x * v.x + v.y * v.y + v.z * v.z + v.w * v.w;
    #pragma unroll
    for (int o = 16; o; o >>= 1) {
        s += __shfl_xor_sync(0xffffffffu, s, o);
        q += __shfl_xor_sync(0xffffffffu, q, o);
    }
    const int warp = tid >> 5;
    if ((tid & 31) == 0) { ss[warp] = s; sq[warp] = q; }
    __syncthreads();
    if (tid == 0) {
        float S = 0.f, Q = 0.f;
        #pragma unroll
        for (int i = 0; i < 8; i++) { S += ss[i]; Q += sq[i]; }
        float mu  = S * (1.f / 1024.f);
        float var = Q * (1.f / 1024.f) - mu * mu;
        smu = mu;
        srs = rsqrtf(var + 1e-5f);
    }
    __syncthreads();
    float mu = smu, rs = srs;
    float4 gv = g[tid], bv = bt[tid];
    out[base + tid] = make_float4((v.x - mu) * rs * gv.x + bv.x,
                                  (v.y - mu) * rs * gv.y + bv.y,
                                  (v.z - mu) * rs * gv.z + bv.z,
                                  (v.w - mu) * rs * gv.w + bv.w);
}

// ---------------- gate logits + softmax(3) + combine, float4 ----------------
__global__ void gate_combine4(const float4* __restrict__ h,
                              const float4* __restrict__ w2, const float* __restrict__ b2,
                              const float4* __restrict__ s0, const float4* __restrict__ s1,
                              const float4* __restrict__ s2, float4* __restrict__ out)
{
    const int row = blockIdx.x, tid = threadIdx.x;
    const long long base = (long long)row * 256;
    __shared__ float r0[8], r1[8], r2[8];
    __shared__ float w[3];

    float4 hv = h[base + tid];
    float4 wa = w2[tid], wb = w2[256 + tid], wc = w2[512 + tid];
    float p0 = hv.x * wa.x + hv.y * wa.y + hv.z * wa.z + hv.w * wa.w;
    float p1 = hv.x * wb.x + hv.y * wb.y + hv.z * wb.z + hv.w * wb.w;
    float p2 = hv.x * wc.x + hv.y * wc.y + hv.z * wc.z + hv.w * wc.w;
    #pragma unroll
    for (int o = 16; o; o >>= 1) {
        p0 += __shfl_xor_sync(0xffffffffu, p0, o);
        p1 += __shfl_xor_sync(0xffffffffu, p1, o);
        p2 += __shfl_xor_sync(0xffffffffu, p2, o);
    }
    const int warp = tid >> 5;
    if ((tid & 31) == 0) { r0[warp] = p0; r1[warp] = p1; r2[warp] = p2; }
    __syncthreads();
    if (tid == 0) {
        float l0 = b2[0], l1 = b2[1], l2 = b2[2];
        #pragma unroll
        for (int i = 0; i < 8; i++) { l0 += r0[i]; l1 += r1[i]; l2 += r2[i]; }
        float m  = fmaxf(l0, fmaxf(l1, l2));
        float e0 = __expf(l0 - m), e1 = __expf(l1 - m), e2 = __expf(l2 - m);
        float inv = 1.f / (e0 + e1 + e2);
        w[0] = e0 * inv; w[1] = e1 * inv; w[2] = e2 * inv;
    }
    __syncthreads();
    float w0 = w[0], w1 = w[1], w2v = w[2];
    float4 a = s0[base + tid], b = s1[base + tid], c = s2[base + tid];
    out[base + tid] = make_float4(w0 * a.x + w1 * b.x + w2v * c.x,
                                  w0 * a.y + w1 * b.y + w2v * c.y,
                                  w0 * a.z + w1 * b.z + w2v * c.z,
                                  w0 * a.w + w1 * b.w + w2v * c.w);
}

// ---------------- launch ----------------
extern "C" void kernel_launch(void* const* d_in, const int* in_sizes, int n_in,
                              void* d_out, int out_size)
{
    (void)in_sizes; (void)n_in; (void)out_size;

    const float* proto = (const float*)d_in[0];
    const float* img   = (const float*)d_in[1];
    const float* cwi   = (const float*)d_in[2];
    const float* cbi   = (const float*)d_in[3];
    const float* cwo   = (const float*)d_in[4];
    const float* cbo   = (const float*)d_in[5];
    const float* swi   = (const float*)d_in[6];
    const float* sbi   = (const float*)d_in[7];
    const float* swo   = (const float*)d_in[8];
    const float* sbo   = (const float*)d_in[9];
    const float* lwi   = (const float*)d_in[10];
    const float* lbi   = (const float*)d_in[11];
    const float* lwo   = (const float*)d_in[12];
    const float* lbo   = (const float*)d_in[13];
    const float* n1g   = (const float*)d_in[14];
    const float* n1b   = (const float*)d_in[15];
    const float* n2g   = (const float*)d_in[16];
    const float* n2b   = (const float*)d_in[17];
    const float* n3g   = (const float*)d_in[18];
    const float* n3b   = (const float*)d_in[19];
    const float* gw1   = (const float*)d_in[20];
    const float* gb1   = (const float*)d_in[21];
    const float* gw2   = (const float*)d_in[22];
    const float* gb2   = (const float*)d_in[23];

    float* out_upd  = (float*)d_out;
    float* out_attn = (float*)d_out + 8388608;

    float *q, *kv, *qkv, *ob, *rw, *cr, *se, *li, *hb;
    float2* ml;
    cudaGetSymbolAddress((void**)&q,   g_q);
    cudaGetSymbolAddress((void**)&kv,  g_kv);
    cudaGetSymbolAddress((void**)&qkv, g_qkv);
    cudaGetSymbolAddress((void**)&ml,  g_ml);
    cudaGetSymbolAddress((void**)&ob,  g_ob);
    cudaGetSymbolAddress((void**)&rw,  g_rw);
    cudaGetSymbolAddress((void**)&cr,  g_cross);
    cudaGetSymbolAddress((void**)&se,  g_selfo);
    cudaGetSymbolAddress((void**)&li,  g_light);
    cudaGetSymbolAddress((void**)&hb,  g_hb);

    constexpr size_t SM_BIG  = (2 * 128 * 68 + 2 * 256 * 68) * 4;    // 208896 (BK=64)
    constexpr size_t SM_F64  = (128 * 68 + 2 * 32 * 68 + 2 * 32 * 72 + 128 * 36) * 4;
    constexpr size_t SM_F128 = (128 * 132 + 2 * 32 * 132 + 2 * 32 * 136 + 128 * 36) * 4;
    constexpr size_t SM_CM   = (2 * 128 * 68 + 2 * 64 * 68) * 4;     // 104448

    cudaFuncSetAttribute((const void*)gemm_big<false,false>,
                         cudaFuncAttributeMaxDynamicSharedMemorySize, SM_BIG);
    cudaFuncSetAttribute((const void*)gemm_big<true,true>,
                         cudaFuncAttributeMaxDynamicSharedMemorySize, SM_BIG);
    cudaFuncSetAttribute((const void*)flash2<64,1024,2,true>,
                         cudaFuncAttributeMaxDynamicSharedMemorySize, SM_F64);
    cudaFuncSetAttribute((const void*)flash2<64,512,2,false>,
                         cudaFuncAttributeMaxDynamicSharedMemorySize, SM_F64);
    cudaFuncSetAttribute((const void*)flash2<128,512,1,false>,
                         cudaFuncAttributeMaxDynamicSharedMemorySize, SM_F128);
    cudaFuncSetAttribute((const void*)cross_mean,
                         cudaFuncAttributeMaxDynamicSharedMemorySize, SM_CM);

    // Side stream + events for the cross_mean fork (created per call;
    // not destroyed — destroying during graph capture invalidates it).
    cudaStream_t s2;
    cudaStreamCreateWithFlags(&s2, cudaStreamNonBlocking);
    cudaEvent_t evF, evJ;
    cudaEventCreateWithFlags(&evF, cudaEventDisableTiming);
    cudaEventCreateWithFlags(&evJ, cudaEventDisableTiming);

    // ============ cross attention (H=16, hd=64, kv=1024) — flash ============
    gemm_big<false,false><<<dim3(4,64),256,SM_BIG>>>(
        proto,nullptr,nullptr,1024,  cwi,1024,  q,1024,  1024, cbi, nullptr);
    gemm_big<false,false><<<dim3(8,128),256,SM_BIG>>>(
        img,nullptr,nullptr,1024,  cwi+1048576,1024,  kv,2048,  1024, cbi+1024, nullptr);
    flash2<64,1024,2,true><<<dim3(4,256),256,SM_F64>>>(
        q,       524288LL,64LL,1024,
        kv,      2097152LL,64LL,2048,
        kv+1024, 2097152LL,64LL,2048,
        ob, 524288LL,64LL,1024,
        ml, 16, 0.125f);

    // fork: cross_mean on side stream (co-residency-sized: 102KB smem)
    cudaEventRecord(evF, 0);
    cudaStreamWaitEvent(s2, evF, 0);
    cross_mean<<<dim3(4,16,16),256,SM_CM,s2>>>(q, kv, ml, out_attn);
    cudaEventRecord(evJ, s2);

    gemm_big<false,false><<<dim3(4,64),256,SM_BIG>>>(
        ob,nullptr,nullptr,1024,  cwo,1024,  rw,1024,  1024, cbo, proto);
    ln4<<<8192,256>>>((const float4*)rw,(const float4*)n1g,(const float4*)n1b,(float4*)cr);

    // ============ self attention (H=16, hd=64, kv=512) — flash ============
    gemm_big<false,false><<<dim3(12,64),256,SM_BIG>>>(
        cr,nullptr,nullptr,1024,  swi,1024,  qkv,3072,  1024, sbi, nullptr);
    flash2<64,512,2,false><<<dim3(4,256),256,SM_F64>>>(
        qkv,      1572864LL,64LL,3072,
        qkv+1024, 1572864LL,64LL,3072,
        qkv+2048, 1572864LL,64LL,3072,
        ob, 524288LL,64LL,1024,
        nullptr, 16, 0.125f);
    gemm_big<false,false><<<dim3(4,64),256,SM_BIG>>>(
        ob,nullptr,nullptr,1024,  swo,1024,  rw,1024,  1024, sbo, cr);
    ln4<<<8192,256>>>((const float4*)rw,(const float4*)n2g,(const float4*)n2b,(float4*)se);

    // ============ light attention (H=8, hd=128, kv=512) — flash ============
    gemm_big<false,false><<<dim3(12,64),256,SM_BIG>>>(
        se,nullptr,nullptr,1024,  lwi,1024,  qkv,3072,  1024, lbi, nullptr);
    flash2<128,512,1,false><<<dim3(4,128),256,SM_F128>>>(
        qkv,      1572864LL,128LL,3072,
        qkv+1024, 1572864LL,128LL,3072,
        qkv+2048, 1572864LL,128LL,3072,
        ob, 524288LL,128LL,1024,
        nullptr, 8, 0.08838834764831845f);
    gemm_big<false,false><<<dim3(4,64),256,SM_BIG>>>(
        ob,nullptr,nullptr,1024,  lwo,1024,  rw,1024,  1024, lbo, se);
    ln4<<<8192,256>>>((const float4*)rw,(const float4*)n3g,(const float4*)n3b,(float4*)li);

    // ============ gate MLP (single K=3072 GEMM, GELU fused) ============
    gemm_big<true,true><<<dim3(4,64),256,SM_BIG>>>(
        cr,se,li,1024,  gw1,3072,  hb,1024,  3072, gb1, nullptr);

    // join side stream before the final kernel
    cudaStreamWaitEvent(0, evJ, 0);

    // ============ gate softmax(3) + combine ============
    gate_combine4<<<8192,256>>>((const float4*)hb,(const float4*)gw2,gb2,
                                (const float4*)cr,(const float4*)se,(const float4*)li,
                                (float4*)out_upd);
}